// round 12
// baseline (speedup 1.0000x reference)
#include <cuda_runtime.h>
#include <cuda_bf16.h>
#include <cuda_fp16.h>

#define NTOK 16384
#define INF  512
#define HID  256
#define OUTF 16
#define NSTEPS 16
#define SIGMA2F 0.1f
#define LSCALE 16384.0f                 // 2^14: lifts L into e4m3 range
#define FIN_SCALE (SIGMA2F / LSCALE)
#define KSPLITS 32
#define KSEG (NTOK / KSPLITS)          // 512
#define KB_TOTAL (NTOK / 32)           // 512 32-k blocks
#define RT_TOTAL (NTOK / 16)           // 1024 row-tiles
#define SLICES_PER_CTA (KSEG / 32)     // 16
#define RGROUPS (RT_TOTAL / 8)         // 128 row-groups (128 rows each)
#define INIT_CTAS (NTOK / 8)           // 2048
#define CONV_CTAS (RT_TOTAL * 64)      // 65536

// Scratch (device globals: sanctioned, no allocation)
// g_L8: L e4m3, k32-fragment-major: block (rt, kb) -> 512B, lane l -> uint4
__device__ __align__(16) uint4          g_L8[(size_t)RT_TOTAL * KB_TOTAL * 32];  // 256 MB
__device__ __align__(16) float          g_U[2][NTOK * OUTF];                     // u fp32 master
__device__ __align__(16) unsigned char  g_B8[2][NTOK * OUTF];                    // u e4m3 B-frag-major
__device__ __align__(16) float          g_P[NTOK * OUTF];                        // partials (zero steady)
__device__ unsigned                     g_cnt[RGROUPS];                          // completion counters (zero steady)

// ---------------------------------------------------------------------------
__device__ __forceinline__ unsigned short e4m3x2_pack(float hi, float lo) {
    unsigned short r;
    asm("cvt.rn.satfinite.e4m3x2.f32 %0, %1, %2;" : "=h"(r) : "f"(hi), "f"(lo));
    return r;
}
__device__ __forceinline__ unsigned pack4_e4m3(float4 f, float s) {
    const unsigned lo = e4m3x2_pack(f.y * s, f.x * s);
    const unsigned hi = e4m3x2_pack(f.w * s, f.z * s);
    return lo | (hi << 16);
}

// write one fp32 value (row r = k index, col c) into e4m3 B-fragment layout
__device__ __forceinline__ void write_bfrag8(unsigned char* Bf, int r, int c, float v) {
    const int sl = r >> 5, p = r & 31;
    const int g = c & 7;
    const int ph = p & 15;
    const int lane = g * 4 + (ph >> 2);
    const int word = (p >> 4) + 2 * (c >> 3);
    const unsigned short q = e4m3x2_pack(0.0f, v);
    Bf[sl * 512 + lane * 16 + word * 4 + (ph & 3)] = (unsigned char)(q & 0xFF);
}

// ---------------------------------------------------------------------------
// Fused prologue: blocks [0, INIT_CTAS) = init_u0; rest = convert_L (overlap).
// ---------------------------------------------------------------------------
#define CV_PAD 264
struct ProSmem {
    union {
        struct { float fs[8][INF]; float hs[8][HID]; } init;   // 24 KB
        float cv[16][CV_PAD];                                  // ~16.9 KB
    };
};

__global__ void __launch_bounds__(256) prologue(
    const float* __restrict__ L,
    const float* __restrict__ F,  const float* __restrict__ W1, const float* __restrict__ b1,
    const float* __restrict__ W2, const float* __restrict__ b2,
    const float* __restrict__ Ws, const float* __restrict__ bs)
{
    __shared__ ProSmem sm;
    const int tid = threadIdx.x;

    if (blockIdx.x < INIT_CTAS) {
        // ================= init_u0 =================
        float (*fs)[INF] = sm.init.fs;
        float (*hs)[HID] = sm.init.hs;
        const int rbase = blockIdx.x * 8;

        {
            const float4* Fv = (const float4*)(F + (size_t)rbase * INF);
            float4* fsv = (float4*)&fs[0][0];
            #pragma unroll 4
            for (int i = tid; i < 8 * INF / 4; i += 256) fsv[i] = Fv[i];
        }
        __syncthreads();

        {
            const int j = tid;
            float acc[8];
            const float bb = b1[j];
            #pragma unroll
            for (int rr = 0; rr < 8; rr++) acc[rr] = bb;
            #pragma unroll 4
            for (int k = 0; k < INF; k++) {
                const float w = W1[k * HID + j];
                #pragma unroll
                for (int rr = 0; rr < 8; rr++) acc[rr] = fmaf(fs[rr][k], w, acc[rr]);
            }
            #pragma unroll
            for (int rr = 0; rr < 8; rr++) {
                const float x = acc[rr];
                hs[rr][j] = x > 0.0f ? x : expm1f(x);
            }
        }
        __syncthreads();

        if (tid < 8 * OUTF) {
            const int rr = tid >> 4, c = tid & 15;
            float s0 = bs[c] + b2[c], s1 = 0.f, s2 = 0.f, s3 = 0.f;
            #pragma unroll 4
            for (int k = 0; k < INF; k += 4) {
                s0 = fmaf(fs[rr][k + 0], Ws[(k + 0) * OUTF + c], s0);
                s1 = fmaf(fs[rr][k + 1], Ws[(k + 1) * OUTF + c], s1);
                s2 = fmaf(fs[rr][k + 2], Ws[(k + 2) * OUTF + c], s2);
                s3 = fmaf(fs[rr][k + 3], Ws[(k + 3) * OUTF + c], s3);
            }
            #pragma unroll 4
            for (int j = 0; j < HID; j += 4) {
                s0 = fmaf(hs[rr][j + 0], W2[(j + 0) * OUTF + c], s0);
                s1 = fmaf(hs[rr][j + 1], W2[(j + 1) * OUTF + c], s1);
                s2 = fmaf(hs[rr][j + 2], W2[(j + 2) * OUTF + c], s2);
                s3 = fmaf(hs[rr][j + 3], W2[(j + 3) * OUTF + c], s3);
            }
            const float s = (s0 + s1) + (s2 + s3);
            const int r = rbase + rr;
            g_U[0][r * OUTF + c] = s;
            write_bfrag8(g_B8[0], r, c, s);
        }
    } else {
        // ================= convert_L (k32 fragment layout) =================
        float (*s)[CV_PAD] = sm.cv;
        const int blk = blockIdx.x - INIT_CTAS;   // 0..65535
        const int rt = blk >> 6;
        const int kg = blk & 63;

        const float* __restrict__ src = L + (size_t)rt * 16 * NTOK + kg * 256;
        #pragma unroll 4
        for (int j = tid; j < 16 * 64; j += 256) {
            const int row = j >> 6, c4 = j & 63;
            const float4 v = __ldcs((const float4*)(src + (size_t)row * NTOK + c4 * 4));
            *(float4*)&s[row][c4 * 4] = v;
        }
        __syncthreads();

        const int warp = tid >> 5, lane = tid & 31;
        const int g = lane >> 2, t = lane & 3;
        const int kb = kg * 8 + warp;            // global 32-k block
        const int c = warp * 32 + 4 * t;         // local col base

        const float4 f0 = *(const float4*)&s[g][c];
        const float4 f1 = *(const float4*)&s[g + 8][c];
        const float4 f2 = *(const float4*)&s[g][c + 16];
        const float4 f3 = *(const float4*)&s[g + 8][c + 16];
        uint4 o;
        o.x = pack4_e4m3(f0, LSCALE);
        o.y = pack4_e4m3(f1, LSCALE);
        o.z = pack4_e4m3(f2, LSCALE);
        o.w = pack4_e4m3(f3, LSCALE);
        g_L8[((size_t)rt * KB_TOTAL + kb) * 32 + lane] = o;
    }
}

// ---------------------------------------------------------------------------
// Step kernel: partial fp8 GEMM + fused split-K finalize.
// Grid (RGROUPS=128, KSPLITS=32). Last-arriving CTA per row-group finalizes.
// ---------------------------------------------------------------------------
__device__ __forceinline__ void mma16832f8(float d[4], const uint4 a,
                                           unsigned b0, unsigned b1) {
    asm volatile(
        "mma.sync.aligned.m16n8k32.row.col.f32.e4m3.e4m3.f32 "
        "{%0,%1,%2,%3}, {%4,%5,%6,%7}, {%8,%9}, {%0,%1,%2,%3};\n"
        : "+f"(d[0]), "+f"(d[1]), "+f"(d[2]), "+f"(d[3])
        : "r"(a.x), "r"(a.y), "r"(a.z), "r"(a.w), "r"(b0), "r"(b1));
}

__global__ void __launch_bounds__(256, 6) step_fused(int inb, int outb, float* final_dst) {
    __shared__ uint4 sB[SLICES_PER_CTA * 32];   // 8 KB: e4m3 B frags for this K-range
    __shared__ unsigned s_old;

    const int tid  = threadIdx.x;
    const int warp = tid >> 5;
    const int lane = tid & 31;

    const int rg  = blockIdx.x;                         // row-group 0..127
    const int rt  = rg * 8 + warp;                      // row-tile 0..1023
    const int kb0 = blockIdx.y * SLICES_PER_CTA;        // first 32-k block

    {
        const uint4* __restrict__ Bg = reinterpret_cast<const uint4*>(g_B8[inb]) + kb0 * 32;
        #pragma unroll 2
        for (int i = tid; i < SLICES_PER_CTA * 32; i += 256) sB[i] = Bg[i];
    }
    __syncthreads();

    const uint4* __restrict__ Af = g_L8 + ((size_t)rt * KB_TOTAL + kb0) * 32 + lane;

    float d0[4] = {0.f, 0.f, 0.f, 0.f};   // cols 0..7
    float d1[4] = {0.f, 0.f, 0.f, 0.f};   // cols 8..15

    #pragma unroll 2
    for (int c = 0; c < SLICES_PER_CTA; c += 2) {
        const uint4 a0 = __ldcs(Af + (c + 0) * 32);
        const uint4 a1 = __ldcs(Af + (c + 1) * 32);
        const uint4 b0 = sB[(c + 0) * 32 + lane];
        const uint4 b1 = sB[(c + 1) * 32 + lane];
        mma16832f8(d0, a0, b0.x, b0.y);
        mma16832f8(d1, a0, b0.z, b0.w);
        mma16832f8(d0, a1, b1.x, b1.y);
        mma16832f8(d1, a1, b1.z, b1.w);
    }

    {
        const int g = lane >> 2, t2 = 2 * (lane & 3);
        const int r0 = rt * 16 + g, r1 = r0 + 8;
        #pragma unroll
        for (int h = 0; h < 2; h++) {
            const float* dd = h ? d1 : d0;
            const int cc = t2 + 8 * h;
            atomicAdd(&g_P[r0 * OUTF + cc],     dd[0]);
            atomicAdd(&g_P[r0 * OUTF + cc + 1], dd[1]);
            atomicAdd(&g_P[r1 * OUTF + cc],     dd[2]);
            atomicAdd(&g_P[r1 * OUTF + cc + 1], dd[3]);
        }
    }

    // ---- split-K completion protocol (threadFenceReduction pattern) ----
    __threadfence();            // make this CTA's reductions globally visible
    __syncthreads();
    if (tid == 0) s_old = atomicAdd(&g_cnt[rg], 1u);
    __syncthreads();
    if (s_old != KSPLITS - 1) return;

    // Last CTA for this row-group: finalize its 128 rows.
    __threadfence();            // acquire: all other CTAs' reductions visible

    const int r = rg * 128 + (tid >> 1);
    const int c0 = (tid & 1) * 8;
    const float* __restrict__ Ui = g_U[inb] + r * OUTF + c0;
    float* __restrict__ Uo = g_U[outb] + r * OUTF + c0;
    float* __restrict__ P  = g_P + r * OUTF + c0;

    float v[8];
    #pragma unroll
    for (int i = 0; i < 2; i++) {
        float4 u4 = *(const float4*)(Ui + 4 * i);
        float4 p4 = *(const float4*)(P + 4 * i);
        v[4*i+0] = u4.x - FIN_SCALE * p4.x;
        v[4*i+1] = u4.y - FIN_SCALE * p4.y;
        v[4*i+2] = u4.z - FIN_SCALE * p4.z;
        v[4*i+3] = u4.w - FIN_SCALE * p4.w;
        *(float4*)(Uo + 4 * i) = make_float4(v[4*i+0], v[4*i+1], v[4*i+2], v[4*i+3]);
        *(float4*)(P + 4 * i) = make_float4(0.f, 0.f, 0.f, 0.f);
        if (final_dst) *(float4*)(final_dst + r * OUTF + c0 + 4 * i)
            = make_float4(v[4*i+0], v[4*i+1], v[4*i+2], v[4*i+3]);
    }
    unsigned char* __restrict__ Bf = g_B8[outb];
    #pragma unroll
    for (int c = 0; c < 8; c++) write_bfrag8(Bf, r, c0 + c, v[c]);

    if (tid == 0) g_cnt[rg] = 0u;   // reset for next step / next replay
}

// ---------------------------------------------------------------------------
extern "C" void kernel_launch(void* const* d_in, const int* in_sizes, int n_in,
                              void* d_out, int out_size) {
    const float* F  = (const float*)d_in[0];
    const float* L  = (const float*)d_in[1];
    const float* W1 = (const float*)d_in[2];
    const float* b1 = (const float*)d_in[3];
    const float* W2 = (const float*)d_in[4];
    const float* b2 = (const float*)d_in[5];
    const float* Ws = (const float*)d_in[6];
    const float* bs = (const float*)d_in[7];

    prologue<<<INIT_CTAS + CONV_CTAS, 256>>>(L, F, W1, b1, W2, b2, Ws, bs);
    for (int s = 0; s < NSTEPS; s++) {
        dim3 grid(RGROUPS, KSPLITS);
        step_fused<<<grid, 256>>>(s & 1, (s + 1) & 1,
                                  s == NSTEPS - 1 ? (float*)d_out : nullptr);
    }
}

// round 13
// speedup vs baseline: 1.1493x; 1.1493x over previous
#include <cuda_runtime.h>
#include <cuda_bf16.h>
#include <cuda_fp16.h>

#define NTOK 16384
#define INF  512
#define HID  256
#define OUTF 16
#define NSTEPS 16
#define SIGMA2F 0.1f
#define LSCALE 16384.0f                 // 2^14: lifts L into e4m3 range
#define FIN_SCALE (SIGMA2F / LSCALE)
#define KSPLITS 32
#define KSEG (NTOK / KSPLITS)          // 512
#define KB_TOTAL (NTOK / 32)           // 512 32-k blocks
#define RT_TOTAL (NTOK / 16)           // 1024 row-tiles
#define SLICES_PER_CTA (KSEG / 32)     // 16
#define INIT_CTAS (NTOK / 8)           // 2048
#define CONV_CTAS (RT_TOTAL * 64)      // 65536

// Scratch (device globals: sanctioned, no allocation)
// g_L8: L e4m3, k32-fragment-major: block (rt, kb) -> 512B, lane l -> uint4
__device__ __align__(16) uint4          g_L8[(size_t)RT_TOTAL * KB_TOTAL * 32];  // 256 MB
__device__ __align__(16) float          g_U[2][NTOK * OUTF];                     // u fp32 master
__device__ __align__(16) unsigned char  g_B8[2][NTOK * OUTF];                    // u e4m3 B-frag-major
__device__ __align__(16) float          g_P[NTOK * OUTF];                        // partials (zero steady)

// ---------------------------------------------------------------------------
__device__ __forceinline__ unsigned short e4m3x2_pack(float hi, float lo) {
    unsigned short r;
    asm("cvt.rn.satfinite.e4m3x2.f32 %0, %1, %2;" : "=h"(r) : "f"(hi), "f"(lo));
    return r;
}
__device__ __forceinline__ unsigned pack4_e4m3(float4 f, float s) {
    const unsigned lo = e4m3x2_pack(f.y * s, f.x * s);
    const unsigned hi = e4m3x2_pack(f.w * s, f.z * s);
    return lo | (hi << 16);
}

// write one fp32 value (row r = k index, col c) into e4m3 B-fragment layout
__device__ __forceinline__ void write_bfrag8(unsigned char* Bf, int r, int c, float v) {
    const int sl = r >> 5, p = r & 31;
    const int g = c & 7;
    const int ph = p & 15;
    const int lane = g * 4 + (ph >> 2);
    const int word = (p >> 4) + 2 * (c >> 3);
    const unsigned short q = e4m3x2_pack(0.0f, v);
    Bf[sl * 512 + lane * 16 + word * 4 + (ph & 3)] = (unsigned char)(q & 0xFF);
}

// ---------------------------------------------------------------------------
// Fused prologue: blocks [0, INIT_CTAS) = init_u0; rest = convert_L (overlap).
// ---------------------------------------------------------------------------
#define CV_PAD 264
struct ProSmem {
    union {
        struct { float fs[8][INF]; float hs[8][HID]; } init;   // 24 KB
        float cv[16][CV_PAD];                                  // ~16.9 KB
    };
};

__global__ void __launch_bounds__(256) prologue(
    const float* __restrict__ L,
    const float* __restrict__ F,  const float* __restrict__ W1, const float* __restrict__ b1,
    const float* __restrict__ W2, const float* __restrict__ b2,
    const float* __restrict__ Ws, const float* __restrict__ bs)
{
    __shared__ ProSmem sm;
    const int tid = threadIdx.x;

    if (blockIdx.x < INIT_CTAS) {
        // ================= init_u0 =================
        float (*fs)[INF] = sm.init.fs;
        float (*hs)[HID] = sm.init.hs;
        const int rbase = blockIdx.x * 8;

        {
            const float4* Fv = (const float4*)(F + (size_t)rbase * INF);
            float4* fsv = (float4*)&fs[0][0];
            #pragma unroll 4
            for (int i = tid; i < 8 * INF / 4; i += 256) fsv[i] = Fv[i];
        }
        __syncthreads();

        {
            const int j = tid;
            float acc[8];
            const float bb = b1[j];
            #pragma unroll
            for (int rr = 0; rr < 8; rr++) acc[rr] = bb;
            #pragma unroll 4
            for (int k = 0; k < INF; k++) {
                const float w = W1[k * HID + j];
                #pragma unroll
                for (int rr = 0; rr < 8; rr++) acc[rr] = fmaf(fs[rr][k], w, acc[rr]);
            }
            #pragma unroll
            for (int rr = 0; rr < 8; rr++) {
                const float x = acc[rr];
                hs[rr][j] = x > 0.0f ? x : expm1f(x);
            }
        }
        __syncthreads();

        if (tid < 8 * OUTF) {
            const int rr = tid >> 4, c = tid & 15;
            float s0 = bs[c] + b2[c], s1 = 0.f, s2 = 0.f, s3 = 0.f;
            #pragma unroll 4
            for (int k = 0; k < INF; k += 4) {
                s0 = fmaf(fs[rr][k + 0], Ws[(k + 0) * OUTF + c], s0);
                s1 = fmaf(fs[rr][k + 1], Ws[(k + 1) * OUTF + c], s1);
                s2 = fmaf(fs[rr][k + 2], Ws[(k + 2) * OUTF + c], s2);
                s3 = fmaf(fs[rr][k + 3], Ws[(k + 3) * OUTF + c], s3);
            }
            #pragma unroll 4
            for (int j = 0; j < HID; j += 4) {
                s0 = fmaf(hs[rr][j + 0], W2[(j + 0) * OUTF + c], s0);
                s1 = fmaf(hs[rr][j + 1], W2[(j + 1) * OUTF + c], s1);
                s2 = fmaf(hs[rr][j + 2], W2[(j + 2) * OUTF + c], s2);
                s3 = fmaf(hs[rr][j + 3], W2[(j + 3) * OUTF + c], s3);
            }
            const float s = (s0 + s1) + (s2 + s3);
            const int r = rbase + rr;
            g_U[0][r * OUTF + c] = s;
            write_bfrag8(g_B8[0], r, c, s);
        }
    } else {
        // ================= convert_L (k32 fragment layout) =================
        float (*s)[CV_PAD] = sm.cv;
        const int blk = blockIdx.x - INIT_CTAS;   // 0..65535
        const int rt = blk >> 6;
        const int kg = blk & 63;

        const float* __restrict__ src = L + (size_t)rt * 16 * NTOK + kg * 256;
        #pragma unroll 4
        for (int j = tid; j < 16 * 64; j += 256) {
            const int row = j >> 6, c4 = j & 63;
            const float4 v = __ldcs((const float4*)(src + (size_t)row * NTOK + c4 * 4));
            *(float4*)&s[row][c4 * 4] = v;
        }
        __syncthreads();

        const int warp = tid >> 5, lane = tid & 31;
        const int g = lane >> 2, t = lane & 3;
        const int kb = kg * 8 + warp;            // global 32-k block
        const int c = warp * 32 + 4 * t;         // local col base

        const float4 f0 = *(const float4*)&s[g][c];
        const float4 f1 = *(const float4*)&s[g + 8][c];
        const float4 f2 = *(const float4*)&s[g][c + 16];
        const float4 f3 = *(const float4*)&s[g + 8][c + 16];
        uint4 o;
        o.x = pack4_e4m3(f0, LSCALE);
        o.y = pack4_e4m3(f1, LSCALE);
        o.z = pack4_e4m3(f2, LSCALE);
        o.w = pack4_e4m3(f3, LSCALE);
        g_L8[((size_t)rt * KB_TOTAL + kb) * 32 + lane] = o;
    }
}

// ---------------------------------------------------------------------------
// Kernel 3: partial GEMM, full fp8 (e4m3 x e4m3, m16n8k32). Grid (128, 32).
// Mainloop fully unrolled in groups of 4 slices -> 4 LDG.128 front-batched
// (MLP=4/warp: ~24 KB in flight per SM, covers DRAM latency at 5+ TB/s).
// ---------------------------------------------------------------------------
__device__ __forceinline__ void mma16832f8(float d[4], const uint4 a,
                                           unsigned b0, unsigned b1) {
    asm volatile(
        "mma.sync.aligned.m16n8k32.row.col.f32.e4m3.e4m3.f32 "
        "{%0,%1,%2,%3}, {%4,%5,%6,%7}, {%8,%9}, {%0,%1,%2,%3};\n"
        : "+f"(d[0]), "+f"(d[1]), "+f"(d[2]), "+f"(d[3])
        : "r"(a.x), "r"(a.y), "r"(a.z), "r"(a.w), "r"(b0), "r"(b1));
}

__global__ void __launch_bounds__(256, 6) step_partial(int inb) {
    __shared__ uint4 sB[SLICES_PER_CTA * 32];   // 8 KB: e4m3 B frags for this K-range

    const int tid  = threadIdx.x;
    const int warp = tid >> 5;
    const int lane = tid & 31;

    const int rt  = blockIdx.x * 8 + warp;              // row-tile 0..1023
    const int kb0 = blockIdx.y * SLICES_PER_CTA;        // first 32-k block

    {
        const uint4* __restrict__ Bg = reinterpret_cast<const uint4*>(g_B8[inb]) + kb0 * 32;
        #pragma unroll 2
        for (int i = tid; i < SLICES_PER_CTA * 32; i += 256) sB[i] = Bg[i];
    }
    __syncthreads();

    const uint4* __restrict__ Af = g_L8 + ((size_t)rt * KB_TOTAL + kb0) * 32 + lane;

    float d0[4] = {0.f, 0.f, 0.f, 0.f};   // cols 0..7
    float d1[4] = {0.f, 0.f, 0.f, 0.f};   // cols 8..15

    #pragma unroll
    for (int c = 0; c < SLICES_PER_CTA; c += 4) {
        // front-batch 4 independent LDG.128 (MLP=4)
        const uint4 a0 = __ldcs(Af + (c + 0) * 32);
        const uint4 a1 = __ldcs(Af + (c + 1) * 32);
        const uint4 a2 = __ldcs(Af + (c + 2) * 32);
        const uint4 a3 = __ldcs(Af + (c + 3) * 32);
        const uint4 b0 = sB[(c + 0) * 32 + lane];
        const uint4 b1 = sB[(c + 1) * 32 + lane];
        const uint4 b2 = sB[(c + 2) * 32 + lane];
        const uint4 b3 = sB[(c + 3) * 32 + lane];
        mma16832f8(d0, a0, b0.x, b0.y);
        mma16832f8(d1, a0, b0.z, b0.w);
        mma16832f8(d0, a1, b1.x, b1.y);
        mma16832f8(d1, a1, b1.z, b1.w);
        mma16832f8(d0, a2, b2.x, b2.y);
        mma16832f8(d1, a2, b2.z, b2.w);
        mma16832f8(d0, a3, b3.x, b3.y);
        mma16832f8(d1, a3, b3.z, b3.w);
    }

    const int g = lane >> 2, t2 = 2 * (lane & 3);
    const int r0 = rt * 16 + g, r1 = r0 + 8;
    #pragma unroll
    for (int h = 0; h < 2; h++) {
        const float* dd = h ? d1 : d0;
        const int cc = t2 + 8 * h;
        atomicAdd(&g_P[r0 * OUTF + cc],     dd[0]);
        atomicAdd(&g_P[r0 * OUTF + cc + 1], dd[1]);
        atomicAdd(&g_P[r1 * OUTF + cc],     dd[2]);
        atomicAdd(&g_P[r1 * OUTF + cc + 1], dd[3]);
    }
}

// ---------------------------------------------------------------------------
// Kernel 4: finalize. u_out = u_in - (sigma2/LSCALE) * P; rezero P; emit B8.
// ---------------------------------------------------------------------------
__global__ void __launch_bounds__(256) step_finalize(int inb, int outb, float* final_dst) {
    const int idx = blockIdx.x * 256 + threadIdx.x;   // 0..32767
    const int r = idx >> 1;
    const int c0 = (idx & 1) * 8;

    const float* __restrict__ Ui = g_U[inb] + r * OUTF + c0;
    float* __restrict__ Uo = g_U[outb] + r * OUTF + c0;
    float* __restrict__ P  = g_P + r * OUTF + c0;

    float v[8];
    #pragma unroll
    for (int i = 0; i < 2; i++) {
        float4 u4 = *(const float4*)(Ui + 4 * i);
        float4 p4 = *(const float4*)(P + 4 * i);
        v[4*i+0] = u4.x - FIN_SCALE * p4.x;
        v[4*i+1] = u4.y - FIN_SCALE * p4.y;
        v[4*i+2] = u4.z - FIN_SCALE * p4.z;
        v[4*i+3] = u4.w - FIN_SCALE * p4.w;
        *(float4*)(Uo + 4 * i) = make_float4(v[4*i+0], v[4*i+1], v[4*i+2], v[4*i+3]);
        *(float4*)(P + 4 * i) = make_float4(0.f, 0.f, 0.f, 0.f);
        if (final_dst) *(float4*)(final_dst + r * OUTF + c0 + 4 * i)
            = make_float4(v[4*i+0], v[4*i+1], v[4*i+2], v[4*i+3]);
    }
    unsigned char* __restrict__ Bf = g_B8[outb];
    #pragma unroll
    for (int c = 0; c < 8; c++) write_bfrag8(Bf, r, c0 + c, v[c]);
}

// ---------------------------------------------------------------------------
extern "C" void kernel_launch(void* const* d_in, const int* in_sizes, int n_in,
                              void* d_out, int out_size) {
    const float* F  = (const float*)d_in[0];
    const float* L  = (const float*)d_in[1];
    const float* W1 = (const float*)d_in[2];
    const float* b1 = (const float*)d_in[3];
    const float* W2 = (const float*)d_in[4];
    const float* b2 = (const float*)d_in[5];
    const float* Ws = (const float*)d_in[6];
    const float* bs = (const float*)d_in[7];

    prologue<<<INIT_CTAS + CONV_CTAS, 256>>>(L, F, W1, b1, W2, b2, Ws, bs);
    for (int s = 0; s < NSTEPS; s++) {
        dim3 grid(RT_TOTAL / 8, KSPLITS);
        step_partial<<<grid, 256>>>(s & 1);
        step_finalize<<<NTOK * 2 / 256, 256>>>(s & 1, (s + 1) & 1,
                                               s == NSTEPS - 1 ? (float*)d_out : nullptr);
    }
}